// round 13
// baseline (speedup 1.0000x reference)
#include <cuda_runtime.h>
#include <cuda_fp16.h>
#include <cstdint>
#include <math.h>

#define BB 32
#define CC 1024
#define QQ 128
#define DD 256
#define FF 1024
#define MM (BB * CC)

// ---- scratch: device globals (no allocations allowed) ----
__device__ float g_c2q[BB * CC * DD];
__device__ float g_m[BB * CC];
__device__ float g_qw[BB * QQ];
__device__ float g_cw[BB * CC];
__device__ float g_q2c[BB * DD];
__device__ __half g_a16[(size_t)MM * FF];     // att, fp16 (64 MB)
__device__ __half g_h16[(size_t)MM * FF];     // h,   fp16 (64 MB)
__device__ __half g_w1[FF * FF];              // W1 fp16
__device__ __half g_w2[FF * FF];              // W2 fp16

#define CP16(smem_b, gptr) \
    asm volatile("cp.async.cg.shared.global [%0], [%1], 16;" :: "r"(smem_b), "l"(gptr))

// ================= K0: qw[b,q]=q.wq ; cw[b,c]=c.wc =================
__global__ void k_dots(const float* __restrict__ q, const float* __restrict__ ctx,
                       const float* __restrict__ wq, const float* __restrict__ wc)
{
    int w = (blockIdx.x * blockDim.x + threadIdx.x) >> 5;
    int lane = threadIdx.x & 31;
    const int NQ = BB * QQ, NC = BB * CC;
    if (w < NQ) {
        const float* v = q + (size_t)w * DD;
        float s = 0.f;
        #pragma unroll
        for (int i = 0; i < DD / 32; i++) s = fmaf(v[lane + i * 32], wq[lane + i * 32], s);
        #pragma unroll
        for (int o = 16; o; o >>= 1) s += __shfl_xor_sync(0xffffffffu, s, o);
        if (!lane) g_qw[w] = s;
    } else if (w < NQ + NC) {
        int ww = w - NQ;
        const float* v = ctx + (size_t)ww * DD;
        float s = 0.f;
        #pragma unroll
        for (int i = 0; i < DD / 32; i++) s = fmaf(v[lane + i * 32], wc[lane + i * 32], s);
        #pragma unroll
        for (int o = 16; o; o >>= 1) s += __shfl_xor_sync(0xffffffffu, s, o);
        if (!lane) g_cw[ww] = s;
    }
}

// ============ K1: fused sim -> softmax -> c2q (exact fp32) ============
#define K1_SMEM_BYTES (28032 * 4)
__global__ void __launch_bounds__(256) k_attn(
    const float* __restrict__ ctx, const float* __restrict__ question,
    const float* __restrict__ wm)
{
    extern __shared__ float sm[];
    float* Ps    = sm;
    float* Qs2   = sm + 16896;
    float* red   = sm + 25600;
    float* rowm  = sm + 27776;
    float* rowiv = sm + 27904;
    float* Cs    = Ps;
    float* Qs    = Ps + 4224;

    const int b = blockIdx.y, c0 = blockIdx.x << 7;
    const int tid = threadIdx.x, tx = tid & 15, ty = tid >> 4;
    const float* ctxb = ctx + ((size_t)b * CC + c0) * DD;
    const float* qb   = question + (size_t)b * QQ * DD;

    float acc[8][8];
    #pragma unroll
    for (int i = 0; i < 8; i++)
        #pragma unroll
        for (int j = 0; j < 8; j++) acc[i][j] = 0.f;

    for (int dc = 0; dc < DD; dc += 32) {
        #pragma unroll
        for (int i = 0; i < 4; i++) {
            int idx = tid + (i << 8);
            int row = idx >> 3, kk = (idx & 7) << 2;
            float4 v = *(const float4*)(ctxb + (size_t)row * DD + dc + kk);
            Cs[(kk + 0) * 132 + row] = v.x;
            Cs[(kk + 1) * 132 + row] = v.y;
            Cs[(kk + 2) * 132 + row] = v.z;
            Cs[(kk + 3) * 132 + row] = v.w;
            float4 u  = *(const float4*)(qb + (size_t)row * DD + dc + kk);
            float4 w4 = *(const float4*)(wm + dc + kk);
            Qs[(kk + 0) * 132 + row] = u.x * w4.x;
            Qs[(kk + 1) * 132 + row] = u.y * w4.y;
            Qs[(kk + 2) * 132 + row] = u.z * w4.z;
            Qs[(kk + 3) * 132 + row] = u.w * w4.w;
        }
        __syncthreads();
        #pragma unroll 8
        for (int k = 0; k < 32; k++) {
            float4 a0 = *(const float4*)&Cs[k * 132 + (ty << 3)];
            float4 a1 = *(const float4*)&Cs[k * 132 + (ty << 3) + 4];
            float4 b0 = *(const float4*)&Qs[k * 132 + (tx << 3)];
            float4 b1 = *(const float4*)&Qs[k * 132 + (tx << 3) + 4];
            float ar[8] = {a0.x, a0.y, a0.z, a0.w, a1.x, a1.y, a1.z, a1.w};
            float br[8] = {b0.x, b0.y, b0.z, b0.w, b1.x, b1.y, b1.z, b1.w};
            #pragma unroll
            for (int i = 0; i < 8; i++)
                #pragma unroll
                for (int j = 0; j < 8; j++)
                    acc[i][j] = fmaf(ar[i], br[j], acc[i][j]);
        }
        __syncthreads();
    }

    float cb[8], qbv[8];
    #pragma unroll
    for (int i = 0; i < 8; i++) cb[i] = g_cw[b * CC + c0 + (ty << 3) + i];
    #pragma unroll
    for (int j = 0; j < 8; j++) qbv[j] = g_qw[b * QQ + (tx << 3) + j];
    #pragma unroll
    for (int i = 0; i < 8; i++)
        #pragma unroll
        for (int j = 0; j < 8; j++) acc[i][j] += cb[i] + qbv[j];

    #pragma unroll
    for (int i = 0; i < 8; i++) {
        float m = acc[i][0];
        #pragma unroll
        for (int j = 1; j < 8; j++) m = fmaxf(m, acc[i][j]);
        red[((ty << 3) + i) * 17 + tx] = m;
    }
    __syncthreads();
    if (tid < 128) {
        float m = red[tid * 17];
        #pragma unroll
        for (int t = 1; t < 16; t++) m = fmaxf(m, red[tid * 17 + t]);
        rowm[tid] = m;
        g_m[b * CC + c0 + tid] = m;
    }
    __syncthreads();
    #pragma unroll
    for (int i = 0; i < 8; i++) {
        float rm = rowm[(ty << 3) + i];
        float s = 0.f;
        #pragma unroll
        for (int j = 0; j < 8; j++) { acc[i][j] = expf(acc[i][j] - rm); s += acc[i][j]; }
        red[((ty << 3) + i) * 17 + tx] = s;
    }
    __syncthreads();
    if (tid < 128) {
        float s = 0.f;
        #pragma unroll
        for (int t = 0; t < 16; t++) s += red[tid * 17 + t];
        rowiv[tid] = 1.0f / s;
    }
    __syncthreads();
    #pragma unroll
    for (int i = 0; i < 8; i++) {
        float riv = rowiv[(ty << 3) + i];
        #pragma unroll
        for (int j = 0; j < 8; j++)
            Ps[((tx << 3) + j) * 132 + (ty << 3) + i] = acc[i][j] * riv;
    }
    __syncthreads();

    float* outp = g_c2q + ((size_t)b * CC + c0) * DD;
    for (int db = 0; db < DD; db += 64) {
        #pragma unroll
        for (int i = 0; i < 8; i++) {
            int idx = tid + (i << 8);
            int qrow = idx >> 4, c4 = (idx & 15) << 2;
            *(float4*)&Qs2[qrow * 68 + c4] = *(const float4*)(qb + (size_t)qrow * DD + db + c4);
        }
        __syncthreads();
        float o[8][4];
        #pragma unroll
        for (int i = 0; i < 8; i++)
            #pragma unroll
            for (int j = 0; j < 4; j++) o[i][j] = 0.f;
        #pragma unroll 8
        for (int qk = 0; qk < 128; qk++) {
            float4 p0 = *(const float4*)&Ps[qk * 132 + (ty << 3)];
            float4 p1 = *(const float4*)&Ps[qk * 132 + (ty << 3) + 4];
            float4 qv = *(const float4*)&Qs2[qk * 68 + (tx << 2)];
            float pr[8] = {p0.x, p0.y, p0.z, p0.w, p1.x, p1.y, p1.z, p1.w};
            #pragma unroll
            for (int i = 0; i < 8; i++) {
                o[i][0] = fmaf(pr[i], qv.x, o[i][0]);
                o[i][1] = fmaf(pr[i], qv.y, o[i][1]);
                o[i][2] = fmaf(pr[i], qv.z, o[i][2]);
                o[i][3] = fmaf(pr[i], qv.w, o[i][3]);
            }
        }
        #pragma unroll
        for (int i = 0; i < 8; i++)
            *(float4*)&outp[(size_t)((ty << 3) + i) * DD + db + (tx << 2)] =
                make_float4(o[i][0], o[i][1], o[i][2], o[i][3]);
        __syncthreads();
    }
}

// ============ K2: q2c[b,d] = softmax_c(rowmax) . context ============
__global__ void k_q2c(const float* __restrict__ ctx)
{
    __shared__ float w[CC];
    __shared__ float red[256];
    const int b = blockIdx.x, tid = threadIdx.x;
    float lm = -1e30f;
    for (int c = tid; c < CC; c += 256) { float v = g_m[b * CC + c]; w[c] = v; lm = fmaxf(lm, v); }
    red[tid] = lm; __syncthreads();
    for (int s = 128; s > 0; s >>= 1) { if (tid < s) red[tid] = fmaxf(red[tid], red[tid + s]); __syncthreads(); }
    float mx = red[0]; __syncthreads();
    float ls = 0.f;
    for (int c = tid; c < CC; c += 256) { float e = expf(w[c] - mx); w[c] = e; ls += e; }
    red[tid] = ls; __syncthreads();
    for (int s = 128; s > 0; s >>= 1) { if (tid < s) red[tid] += red[tid + s]; __syncthreads(); }
    float inv = 1.0f / red[0]; __syncthreads();
    float accv = 0.f;
    const float* cb = ctx + (size_t)b * CC * DD + tid;
    for (int c = 0; c < CC; c++) accv = fmaf(w[c], cb[(size_t)c * DD], accv);
    g_q2c[b * DD + tid] = accv * inv;
}

// ============ prep: convert W to fp16 ============
__global__ void k_cvtw(const float* __restrict__ W, __half* __restrict__ H)
{
    int t = blockIdx.x * 256 + threadIdx.x;
    float4 v = *(const float4*)(W + (size_t)t * 4);
    __half h[4];
    h[0] = __float2half_rn(v.x); h[1] = __float2half_rn(v.y);
    h[2] = __float2half_rn(v.z); h[3] = __float2half_rn(v.w);
    *(uint64_t*)(H + (size_t)t * 4) = *(uint64_t*)h;
}

// ============ prep: materialize att as single fp16 ============
__global__ void k_build_att(const float* __restrict__ ctx)
{
    int t = blockIdx.x * 256 + threadIdx.x;
    int r  = t >> 8;
    int c4 = (t & 255) << 2;
    int seg = c4 >> 8, kd = c4 & 255;
    int bb = r >> 10;
    size_t base = (size_t)r * DD + kd;
    float4 av;
    if (seg == 0) {
        av = *(const float4*)(ctx + base);
    } else if (seg == 1) {
        av = *(const float4*)(g_c2q + base);
    } else if (seg == 2) {
        float4 cv = *(const float4*)(ctx + base);
        float4 qv = *(const float4*)(g_c2q + base);
        av = make_float4(cv.x * qv.x, cv.y * qv.y, cv.z * qv.z, cv.w * qv.w);
    } else {
        float4 cv = *(const float4*)(ctx + base);
        float4 qv = *(const float4*)(g_q2c + bb * DD + kd);
        av = make_float4(cv.x * qv.x, cv.y * qv.y, cv.z * qv.z, cv.w * qv.w);
    }
    __half h[4];
    h[0] = __float2half_rn(av.x); h[1] = __float2half_rn(av.y);
    h[2] = __float2half_rn(av.z); h[3] = __float2half_rn(av.w);
    *(uint64_t*)(g_a16 + (size_t)r * FF + c4) = *(uint64_t*)h;
}

// ============ GEMM: fp16 x fp16 fp32-acc, 256x128 block tile, 3-stage ============
// 8 warps as 4x2 -> warp tile 64x64. One __syncthreads per k-tile.
// stage (halfs, SROW=40): A[256*40]=20480B  B[128*40]=10240B  -> 30720B; x3 stages = 92160B
#define SROW 40
#define ST_BYTES 30720
#define GEMM_SMEM (3 * ST_BYTES)

__device__ __forceinline__ void mma_f16(float* c, const uint32_t* a, uint32_t b0, uint32_t b1) {
    asm volatile(
        "mma.sync.aligned.m16n8k16.row.col.f32.f16.f16.f32 "
        "{%0,%1,%2,%3},{%4,%5,%6,%7},{%8,%9},{%0,%1,%2,%3};"
        : "+f"(c[0]), "+f"(c[1]), "+f"(c[2]), "+f"(c[3])
        : "r"(a[0]), "r"(a[1]), "r"(a[2]), "r"(a[3]), "r"(b0), "r"(b1));
}

template <int MODE>
__global__ void __launch_bounds__(256, 1) k_gemm(
    const __half* __restrict__ A_g, const __half* __restrict__ B_g,
    const float* __restrict__ bias, const int* __restrict__ mask,
    float* __restrict__ out)
{
    extern __shared__ uint16_t sm16[];
    const int tid = threadIdx.x, lane = tid & 31, wrp = tid >> 5;
    const int g = lane >> 2, t4 = lane & 3;
    const int wm0 = (wrp >> 1) << 6;      // 0,64,128,192
    const int wn0 = (wrp & 1) << 6;       // 0,64
    const int m0 = blockIdx.x << 8, n0 = blockIdx.y << 7;
    const int bb = m0 >> 10;

    float acc[4][8][4];
    #pragma unroll
    for (int i = 0; i < 4; i++)
        #pragma unroll
        for (int j = 0; j < 8; j++)
            #pragma unroll
            for (int l = 0; l < 4; l++) acc[i][j][l] = 0.f;

    const uint32_t sbase = (uint32_t)__cvta_generic_to_shared(sm16);

    // stage: A (256 rows x 32 halfs, SROW pad) then B (128 rows)
    auto load_stage = [&](int s, int kt) {
        const int k0 = kt << 5;
        const uint32_t sb = sbase + s * ST_BYTES;
        #pragma unroll
        for (int j = 0; j < 6; j++) {
            int v = tid + (j << 8);            // 0..1535 vec16 ids
            uint32_t soff;
            const __half* gp;
            if (v < 1024) {                    // A: 256 rows x 4 vec
                int row = v >> 2, q = v & 3;
                soff = sb + (uint32_t)(row * SROW + q * 8) * 2;
                gp = A_g + (size_t)(m0 + row) * FF + k0 + q * 8;
            } else {                           // B: 128 rows x 4 vec
                int mv = v - 1024;
                int row = mv >> 2, q = mv & 3;
                soff = sb + 20480u + (uint32_t)(row * SROW + q * 8) * 2;
                gp = B_g + (size_t)(n0 + row) * FF + k0 + q * 8;
            }
            CP16(soff, gp);
        }
        asm volatile("cp.async.commit_group;");
    };

    load_stage(0, 0);
    load_stage(1, 1);

    for (int kt = 0; kt < FF / 32; kt++) {
        const int cur = kt % 3;
        asm volatile("cp.async.wait_group 1;");
        __syncthreads();
        if (kt + 2 < FF / 32) load_stage((kt + 2) % 3, kt + 2);

        const uint16_t* As = sm16 + cur * (ST_BYTES / 2);
        const uint16_t* Bs = As + 10240;

        #pragma unroll
        for (int ks = 0; ks < 32; ks += 16) {
            uint32_t a[4][4];
            #pragma unroll
            for (int mt = 0; mt < 4; mt++) {
                int fb = (wm0 + mt * 16 + g) * SROW + ks + 2 * t4;
                a[mt][0] = *(const uint32_t*)&As[fb];
                a[mt][1] = *(const uint32_t*)&As[fb + 8 * SROW];
                a[mt][2] = *(const uint32_t*)&As[fb + 8];
                a[mt][3] = *(const uint32_t*)&As[fb + 8 * SROW + 8];
            }
            #pragma unroll
            for (int nf = 0; nf < 8; nf++) {
                int nb = (wn0 + nf * 8 + g) * SROW + ks + 2 * t4;
                uint32_t b0 = *(const uint32_t*)&Bs[nb];
                uint32_t b1 = *(const uint32_t*)&Bs[nb + 8];
                #pragma unroll
                for (int mt = 0; mt < 4; mt++)
                    mma_f16(acc[mt][nf], a[mt], b0, b1);
            }
        }
    }

    __syncthreads();   // all reads done before block exits (stage reuse safety for tail loads)

    // epilogue
    #pragma unroll
    for (int mt = 0; mt < 4; mt++) {
        int r0 = m0 + wm0 + mt * 16 + g;
        float mv0 = mask[bb * CC + (r0 & 1023)] ? 1.f : 0.f;
        float mv1 = mask[bb * CC + ((r0 + 8) & 1023)] ? 1.f : 0.f;
        #pragma unroll
        for (int nf = 0; nf < 8; nf++) {
            int col = n0 + wn0 + nf * 8 + 2 * t4;
            float bz0 = bias[col], bz1 = bias[col + 1];
            float v00 = (acc[mt][nf][0] + bz0) * mv0;
            float v01 = (acc[mt][nf][1] + bz1) * mv0;
            float v10 = (acc[mt][nf][2] + bz0) * mv1;
            float v11 = (acc[mt][nf][3] + bz1) * mv1;
            size_t o0 = (size_t)r0 * FF + col;
            size_t o1 = (size_t)(r0 + 8) * FF + col;
            if (MODE == 0) {
                *(__half2*)(g_h16 + o0) = __floats2half2_rn(v00, v01);
                *(__half2*)(g_h16 + o1) = __floats2half2_rn(v10, v11);
            } else {
                *(float2*)&out[o0] = make_float2(fmaxf(v00, 0.f), fmaxf(v01, 0.f));
                *(float2*)&out[o1] = make_float2(fmaxf(v10, 0.f), fmaxf(v11, 0.f));
            }
        }
    }
}

// =========================== launch ===========================
extern "C" void kernel_launch(void* const* d_in, const int* in_sizes, int n_in,
                              void* d_out, int out_size)
{
    const float* ctx = (const float*)d_in[0];
    const float* qst = (const float*)d_in[1];
    const int*   mask = (const int*)d_in[2];     // bool promoted to int32
    const float* wq = (const float*)d_in[3];
    const float* wc = (const float*)d_in[4];
    const float* wm = (const float*)d_in[5];
    const float* W1 = (const float*)d_in[6];
    const float* b1 = (const float*)d_in[7];
    const float* W2 = (const float*)d_in[8];
    const float* b2 = (const float*)d_in[9];
    float* out = (float*)d_out;

    __half *w1, *w2, *a16, *h16;
    cudaGetSymbolAddress((void**)&w1,  g_w1);
    cudaGetSymbolAddress((void**)&w2,  g_w2);
    cudaGetSymbolAddress((void**)&a16, g_a16);
    cudaGetSymbolAddress((void**)&h16, g_h16);

    cudaFuncSetAttribute(k_attn, cudaFuncAttributeMaxDynamicSharedMemorySize, K1_SMEM_BYTES);
    cudaFuncSetAttribute(k_gemm<0>, cudaFuncAttributeMaxDynamicSharedMemorySize, GEMM_SMEM);
    cudaFuncSetAttribute(k_gemm<1>, cudaFuncAttributeMaxDynamicSharedMemorySize, GEMM_SMEM);

    k_cvtw<<<FF * FF / 4 / 256, 256>>>(W1, w1);
    k_cvtw<<<FF * FF / 4 / 256, 256>>>(W2, w2);

    int nwarps = BB * QQ + BB * CC;
    k_dots<<<(nwarps + 7) / 8, 256>>>(qst, ctx, wq, wc);
    k_attn<<<dim3(CC / 128, BB), 256, K1_SMEM_BYTES>>>(ctx, qst, wm);
    k_q2c<<<BB, 256>>>(ctx);
    k_build_att<<<MM, 256>>>(ctx);

    k_gemm<0><<<dim3(MM / 256, FF / 128), 256, GEMM_SMEM>>>(a16, w1, b1, mask, nullptr);
    k_gemm<1><<<dim3(MM / 256, FF / 128), 256, GEMM_SMEM>>>(h16, w2, b2, mask, out);
}

// round 14
// speedup vs baseline: 1.1378x; 1.1378x over previous
#include <cuda_runtime.h>
#include <cuda_fp16.h>
#include <cstdint>
#include <math.h>

#define BB 32
#define CC 1024
#define QQ 128
#define DD 256
#define FF 1024
#define MM (BB * CC)

// ---- scratch: device globals (no allocations allowed) ----
__device__ float g_c2q[BB * CC * DD];
__device__ float g_m[BB * CC];
__device__ float g_qw[BB * QQ];
__device__ float g_cw[BB * CC];
__device__ float g_q2c[BB * DD];
__device__ __half g_a16[(size_t)MM * FF];     // att, fp16 (64 MB)
__device__ __half g_h16[(size_t)MM * FF];     // h,   fp16 (64 MB)
__device__ __half g_w1[FF * FF];              // W1 fp16
__device__ __half g_w2[FF * FF];              // W2 fp16

#define CP16(smem_b, gptr) \
    asm volatile("cp.async.cg.shared.global [%0], [%1], 16;" :: "r"(smem_b), "l"(gptr))

#define LDSM4(r0, r1, r2, r3, addr) \
    asm volatile("ldmatrix.sync.aligned.m8n8.x4.shared.b16 {%0,%1,%2,%3}, [%4];" \
        : "=r"(r0), "=r"(r1), "=r"(r2), "=r"(r3) : "r"(addr))

// ================= K0: qw[b,q]=q.wq ; cw[b,c]=c.wc =================
__global__ void k_dots(const float* __restrict__ q, const float* __restrict__ ctx,
                       const float* __restrict__ wq, const float* __restrict__ wc)
{
    int w = (blockIdx.x * blockDim.x + threadIdx.x) >> 5;
    int lane = threadIdx.x & 31;
    const int NQ = BB * QQ, NC = BB * CC;
    if (w < NQ) {
        const float* v = q + (size_t)w * DD;
        float s = 0.f;
        #pragma unroll
        for (int i = 0; i < DD / 32; i++) s = fmaf(v[lane + i * 32], wq[lane + i * 32], s);
        #pragma unroll
        for (int o = 16; o; o >>= 1) s += __shfl_xor_sync(0xffffffffu, s, o);
        if (!lane) g_qw[w] = s;
    } else if (w < NQ + NC) {
        int ww = w - NQ;
        const float* v = ctx + (size_t)ww * DD;
        float s = 0.f;
        #pragma unroll
        for (int i = 0; i < DD / 32; i++) s = fmaf(v[lane + i * 32], wc[lane + i * 32], s);
        #pragma unroll
        for (int o = 16; o; o >>= 1) s += __shfl_xor_sync(0xffffffffu, s, o);
        if (!lane) g_cw[ww] = s;
    }
}

// ============ K1: fused sim -> softmax -> c2q (exact fp32) ============
#define K1_SMEM_BYTES (28032 * 4)
__global__ void __launch_bounds__(256) k_attn(
    const float* __restrict__ ctx, const float* __restrict__ question,
    const float* __restrict__ wm)
{
    extern __shared__ float sm[];
    float* Ps    = sm;
    float* Qs2   = sm + 16896;
    float* red   = sm + 25600;
    float* rowm  = sm + 27776;
    float* rowiv = sm + 27904;
    float* Cs    = Ps;
    float* Qs    = Ps + 4224;

    const int b = blockIdx.y, c0 = blockIdx.x << 7;
    const int tid = threadIdx.x, tx = tid & 15, ty = tid >> 4;
    const float* ctxb = ctx + ((size_t)b * CC + c0) * DD;
    const float* qb   = question + (size_t)b * QQ * DD;

    float acc[8][8];
    #pragma unroll
    for (int i = 0; i < 8; i++)
        #pragma unroll
        for (int j = 0; j < 8; j++) acc[i][j] = 0.f;

    for (int dc = 0; dc < DD; dc += 32) {
        #pragma unroll
        for (int i = 0; i < 4; i++) {
            int idx = tid + (i << 8);
            int row = idx >> 3, kk = (idx & 7) << 2;
            float4 v = *(const float4*)(ctxb + (size_t)row * DD + dc + kk);
            Cs[(kk + 0) * 132 + row] = v.x;
            Cs[(kk + 1) * 132 + row] = v.y;
            Cs[(kk + 2) * 132 + row] = v.z;
            Cs[(kk + 3) * 132 + row] = v.w;
            float4 u  = *(const float4*)(qb + (size_t)row * DD + dc + kk);
            float4 w4 = *(const float4*)(wm + dc + kk);
            Qs[(kk + 0) * 132 + row] = u.x * w4.x;
            Qs[(kk + 1) * 132 + row] = u.y * w4.y;
            Qs[(kk + 2) * 132 + row] = u.z * w4.z;
            Qs[(kk + 3) * 132 + row] = u.w * w4.w;
        }
        __syncthreads();
        #pragma unroll 8
        for (int k = 0; k < 32; k++) {
            float4 a0 = *(const float4*)&Cs[k * 132 + (ty << 3)];
            float4 a1 = *(const float4*)&Cs[k * 132 + (ty << 3) + 4];
            float4 b0 = *(const float4*)&Qs[k * 132 + (tx << 3)];
            float4 b1 = *(const float4*)&Qs[k * 132 + (tx << 3) + 4];
            float ar[8] = {a0.x, a0.y, a0.z, a0.w, a1.x, a1.y, a1.z, a1.w};
            float br[8] = {b0.x, b0.y, b0.z, b0.w, b1.x, b1.y, b1.z, b1.w};
            #pragma unroll
            for (int i = 0; i < 8; i++)
                #pragma unroll
                for (int j = 0; j < 8; j++)
                    acc[i][j] = fmaf(ar[i], br[j], acc[i][j]);
        }
        __syncthreads();
    }

    float cb[8], qbv[8];
    #pragma unroll
    for (int i = 0; i < 8; i++) cb[i] = g_cw[b * CC + c0 + (ty << 3) + i];
    #pragma unroll
    for (int j = 0; j < 8; j++) qbv[j] = g_qw[b * QQ + (tx << 3) + j];
    #pragma unroll
    for (int i = 0; i < 8; i++)
        #pragma unroll
        for (int j = 0; j < 8; j++) acc[i][j] += cb[i] + qbv[j];

    #pragma unroll
    for (int i = 0; i < 8; i++) {
        float m = acc[i][0];
        #pragma unroll
        for (int j = 1; j < 8; j++) m = fmaxf(m, acc[i][j]);
        red[((ty << 3) + i) * 17 + tx] = m;
    }
    __syncthreads();
    if (tid < 128) {
        float m = red[tid * 17];
        #pragma unroll
        for (int t = 1; t < 16; t++) m = fmaxf(m, red[tid * 17 + t]);
        rowm[tid] = m;
        g_m[b * CC + c0 + tid] = m;
    }
    __syncthreads();
    #pragma unroll
    for (int i = 0; i < 8; i++) {
        float rm = rowm[(ty << 3) + i];
        float s = 0.f;
        #pragma unroll
        for (int j = 0; j < 8; j++) { acc[i][j] = expf(acc[i][j] - rm); s += acc[i][j]; }
        red[((ty << 3) + i) * 17 + tx] = s;
    }
    __syncthreads();
    if (tid < 128) {
        float s = 0.f;
        #pragma unroll
        for (int t = 0; t < 16; t++) s += red[tid * 17 + t];
        rowiv[tid] = 1.0f / s;
    }
    __syncthreads();
    #pragma unroll
    for (int i = 0; i < 8; i++) {
        float riv = rowiv[(ty << 3) + i];
        #pragma unroll
        for (int j = 0; j < 8; j++)
            Ps[((tx << 3) + j) * 132 + (ty << 3) + i] = acc[i][j] * riv;
    }
    __syncthreads();

    float* outp = g_c2q + ((size_t)b * CC + c0) * DD;
    for (int db = 0; db < DD; db += 64) {
        #pragma unroll
        for (int i = 0; i < 8; i++) {
            int idx = tid + (i << 8);
            int qrow = idx >> 4, c4 = (idx & 15) << 2;
            *(float4*)&Qs2[qrow * 68 + c4] = *(const float4*)(qb + (size_t)qrow * DD + db + c4);
        }
        __syncthreads();
        float o[8][4];
        #pragma unroll
        for (int i = 0; i < 8; i++)
            #pragma unroll
            for (int j = 0; j < 4; j++) o[i][j] = 0.f;
        #pragma unroll 8
        for (int qk = 0; qk < 128; qk++) {
            float4 p0 = *(const float4*)&Ps[qk * 132 + (ty << 3)];
            float4 p1 = *(const float4*)&Ps[qk * 132 + (ty << 3) + 4];
            float4 qv = *(const float4*)&Qs2[qk * 68 + (tx << 2)];
            float pr[8] = {p0.x, p0.y, p0.z, p0.w, p1.x, p1.y, p1.z, p1.w};
            #pragma unroll
            for (int i = 0; i < 8; i++) {
                o[i][0] = fmaf(pr[i], qv.x, o[i][0]);
                o[i][1] = fmaf(pr[i], qv.y, o[i][1]);
                o[i][2] = fmaf(pr[i], qv.z, o[i][2]);
                o[i][3] = fmaf(pr[i], qv.w, o[i][3]);
            }
        }
        #pragma unroll
        for (int i = 0; i < 8; i++)
            *(float4*)&outp[(size_t)((ty << 3) + i) * DD + db + (tx << 2)] =
                make_float4(o[i][0], o[i][1], o[i][2], o[i][3]);
        __syncthreads();
    }
}

// ============ K2: q2c[b,d] = softmax_c(rowmax) . context ============
__global__ void k_q2c(const float* __restrict__ ctx)
{
    __shared__ float w[CC];
    __shared__ float red[256];
    const int b = blockIdx.x, tid = threadIdx.x;
    float lm = -1e30f;
    for (int c = tid; c < CC; c += 256) { float v = g_m[b * CC + c]; w[c] = v; lm = fmaxf(lm, v); }
    red[tid] = lm; __syncthreads();
    for (int s = 128; s > 0; s >>= 1) { if (tid < s) red[tid] = fmaxf(red[tid], red[tid + s]); __syncthreads(); }
    float mx = red[0]; __syncthreads();
    float ls = 0.f;
    for (int c = tid; c < CC; c += 256) { float e = expf(w[c] - mx); w[c] = e; ls += e; }
    red[tid] = ls; __syncthreads();
    for (int s = 128; s > 0; s >>= 1) { if (tid < s) red[tid] += red[tid + s]; __syncthreads(); }
    float inv = 1.0f / red[0]; __syncthreads();
    float accv = 0.f;
    const float* cb = ctx + (size_t)b * CC * DD + tid;
    for (int c = 0; c < CC; c++) accv = fmaf(w[c], cb[(size_t)c * DD], accv);
    g_q2c[b * DD + tid] = accv * inv;
}

// ============ prep: convert W to fp16 ============
__global__ void k_cvtw(const float* __restrict__ W, __half* __restrict__ H)
{
    int t = blockIdx.x * 256 + threadIdx.x;
    float4 v = *(const float4*)(W + (size_t)t * 4);
    __half h[4];
    h[0] = __float2half_rn(v.x); h[1] = __float2half_rn(v.y);
    h[2] = __float2half_rn(v.z); h[3] = __float2half_rn(v.w);
    *(uint64_t*)(H + (size_t)t * 4) = *(uint64_t*)h;
}

// ============ prep: materialize att as single fp16 ============
__global__ void k_build_att(const float* __restrict__ ctx)
{
    int t = blockIdx.x * 256 + threadIdx.x;
    int r  = t >> 8;
    int c4 = (t & 255) << 2;
    int seg = c4 >> 8, kd = c4 & 255;
    int bb = r >> 10;
    size_t base = (size_t)r * DD + kd;
    float4 av;
    if (seg == 0) {
        av = *(const float4*)(ctx + base);
    } else if (seg == 1) {
        av = *(const float4*)(g_c2q + base);
    } else if (seg == 2) {
        float4 cv = *(const float4*)(ctx + base);
        float4 qv = *(const float4*)(g_c2q + base);
        av = make_float4(cv.x * qv.x, cv.y * qv.y, cv.z * qv.z, cv.w * qv.w);
    } else {
        float4 cv = *(const float4*)(ctx + base);
        float4 qv = *(const float4*)(g_q2c + bb * DD + kd);
        av = make_float4(cv.x * qv.x, cv.y * qv.y, cv.z * qv.z, cv.w * qv.w);
    }
    __half h[4];
    h[0] = __float2half_rn(av.x); h[1] = __float2half_rn(av.y);
    h[2] = __float2half_rn(av.z); h[3] = __float2half_rn(av.w);
    *(uint64_t*)(g_a16 + (size_t)r * FF + c4) = *(uint64_t*)h;
}

// ============ GEMM: fp16 mma + ldmatrix, 128x128 tile, 3-stage, 2 blk/SM ============
// 8 warps 4x2 -> warp tile 32x64. Single __syncthreads per k-tile.
// stage (halfs, SROW=40): A[128*40] + B[128*40] = 20480B; x3 stages = 61440B
#define SROW 40
#define ST_BYTES 20480
#define GEMM_SMEM (3 * ST_BYTES)
#define NKT (FF / 32)

__device__ __forceinline__ void mma_f16(float* c, const uint32_t* a, uint32_t b0, uint32_t b1) {
    asm volatile(
        "mma.sync.aligned.m16n8k16.row.col.f32.f16.f16.f32 "
        "{%0,%1,%2,%3},{%4,%5,%6,%7},{%8,%9},{%0,%1,%2,%3};"
        : "+f"(c[0]), "+f"(c[1]), "+f"(c[2]), "+f"(c[3])
        : "r"(a[0]), "r"(a[1]), "r"(a[2]), "r"(a[3]), "r"(b0), "r"(b1));
}

template <int MODE>
__global__ void __launch_bounds__(256, 2) k_gemm(
    const __half* __restrict__ A_g, const __half* __restrict__ B_g,
    const float* __restrict__ bias, const int* __restrict__ mask,
    float* __restrict__ out)
{
    extern __shared__ uint16_t sm16[];
    const int tid = threadIdx.x, lane = tid & 31, wrp = tid >> 5;
    const int g = lane >> 2, t4 = lane & 3;
    const int wm0 = (wrp >> 1) << 5;      // 0,32,64,96
    const int wn0 = (wrp & 1) << 6;       // 0,64
    const int m0 = blockIdx.x << 7, n0 = blockIdx.y << 7;
    const int bb = m0 >> 10;

    float acc[2][8][4];
    #pragma unroll
    for (int i = 0; i < 2; i++)
        #pragma unroll
        for (int j = 0; j < 8; j++)
            #pragma unroll
            for (int l = 0; l < 4; l++) acc[i][j][l] = 0.f;

    const uint32_t sbase = (uint32_t)__cvta_generic_to_shared(sm16);
    // ldmatrix lane->address offsets (bytes)
    // A frag (m16k16): lanes 0-7 rows0-7 k0 | 8-15 rows8-15 k0 | 16-23 rows0-7 k8 | 24-31 rows8-15 k8
    const uint32_t aOff = (uint32_t)(((wm0 + (lane & 7) + (((lane >> 3) & 1) << 3)) * SROW
                                     + (((lane >> 4) & 1) << 3)) << 1);
    // B frag pair (2 n-octets x k16): lanes 0-7 n0-7 k0 | 8-15 n0-7 k8 | 16-23 n8-15 k0 | 24-31 n8-15 k8
    const uint32_t bOff = (uint32_t)(((wn0 + (lane & 7) + (((lane >> 4) & 1) << 3)) * SROW
                                     + (((lane >> 3) & 1) << 3)) << 1);

    auto load_stage = [&](int s, int kt) {
        const int k0 = kt << 5;
        const uint32_t sb = sbase + s * ST_BYTES;
        #pragma unroll
        for (int j = 0; j < 4; j++) {
            int v = tid + (j << 8);            // 0..1023 vec16 ids
            int arr = v >> 9;                  // 0=A 1=B
            int mv = v & 511;
            int row = mv >> 2, q = mv & 3;
            uint32_t soff = sb + (uint32_t)arr * 10240u + (uint32_t)((row * SROW + q * 8) << 1);
            const __half* gp = (arr == 0)
                ? A_g + (size_t)(m0 + row) * FF + k0 + q * 8
                : B_g + (size_t)(n0 + row) * FF + k0 + q * 8;
            CP16(soff, gp);
        }
        asm volatile("cp.async.commit_group;");
    };

    load_stage(0, 0);
    load_stage(1, 1);

    for (int kt = 0; kt < NKT; kt++) {
        const int cur = kt % 3;
        if (kt + 1 < NKT) asm volatile("cp.async.wait_group 1;");
        else              asm volatile("cp.async.wait_group 0;");
        __syncthreads();
        if (kt + 2 < NKT) load_stage((kt + 2) % 3, kt + 2);

        const uint32_t stA = sbase + cur * ST_BYTES;
        const uint32_t stB = stA + 10240u;

        #pragma unroll
        for (int ks = 0; ks < 32; ks += 16) {
            uint32_t a[2][4];
            #pragma unroll
            for (int mt = 0; mt < 2; mt++) {
                uint32_t ad = stA + aOff + (uint32_t)(((mt * 16 * SROW) + ks) << 1);
                LDSM4(a[mt][0], a[mt][1], a[mt][2], a[mt][3], ad);
            }
            #pragma unroll
            for (int nf2 = 0; nf2 < 4; nf2++) {
                uint32_t bd = stB + bOff + (uint32_t)(((nf2 * 16 * SROW) + ks) << 1);
                uint32_t b0a, b1a, b0b, b1b;
                LDSM4(b0a, b1a, b0b, b1b, bd);
                mma_f16(acc[0][2 * nf2],     a[0], b0a, b1a);
                mma_f16(acc[1][2 * nf2],     a[1], b0a, b1a);
                mma_f16(acc[0][2 * nf2 + 1], a[0], b0b, b1b);
                mma_f16(acc[1][2 * nf2 + 1], a[1], b0b, b1b);
            }
        }
    }

    // epilogue
    #pragma unroll
    for (int mt = 0; mt < 2; mt++) {
        int r0 = m0 + wm0 + mt * 16 + g;
        float mv0 = mask[bb * CC + (r0 & 1023)] ? 1.f : 0.f;
        float mv1 = mask[bb * CC + ((r0 + 8) & 1023)] ? 1.f : 0.f;
        #pragma unroll
        for (int nf = 0; nf < 8; nf++) {
            int col = n0 + wn0 + nf * 8 + 2 * t4;
            float bz0 = bias[col], bz1 = bias[col + 1];
            float v00 = (acc[mt][nf][0] + bz0) * mv0;
            float v01 = (acc[mt][nf][1] + bz1) * mv0;
            float v10 = (acc[mt][nf][2] + bz0) * mv1;
            float v11 = (acc[mt][nf][3] + bz1) * mv1;
            size_t o0 = (size_t)r0 * FF + col;
            size_t o1 = (size_t)(r0 + 8) * FF + col;
            if (MODE == 0) {
                *(__half2*)(g_h16 + o0) = __floats2half2_rn(v00, v01);
                *(__half2*)(g_h16 + o1) = __floats2half2_rn(v10, v11);
            } else {
                *(float2*)&out[o0] = make_float2(fmaxf(v00, 0.f), fmaxf(v01, 0.f));
                *(float2*)&out[o1] = make_float2(fmaxf(v10, 0.f), fmaxf(v11, 0.f));
            }
        }
    }
}

// =========================== launch ===========================
extern "C" void kernel_launch(void* const* d_in, const int* in_sizes, int n_in,
                              void* d_out, int out_size)
{
    const float* ctx = (const float*)d_in[0];
    const float* qst = (const float*)d_in[1];
    const int*   mask = (const int*)d_in[2];     // bool promoted to int32
    const float* wq = (const float*)d_in[3];
    const float* wc = (const float*)d_in[4];
    const float* wm = (const float*)d_in[5];
    const float* W1 = (const float*)d_in[6];
    const float* b1 = (const float*)d_in[7];
    const float* W2 = (const float*)d_in[8];
    const float* b2 = (const float*)d_in[9];
    float* out = (float*)d_out;

    __half *w1, *w2, *a16, *h16;
    cudaGetSymbolAddress((void**)&w1,  g_w1);
    cudaGetSymbolAddress((void**)&w2,  g_w2);
    cudaGetSymbolAddress((void**)&a16, g_a16);
    cudaGetSymbolAddress((void**)&h16, g_h16);

    cudaFuncSetAttribute(k_attn, cudaFuncAttributeMaxDynamicSharedMemorySize, K1_SMEM_BYTES);
    cudaFuncSetAttribute(k_gemm<0>, cudaFuncAttributeMaxDynamicSharedMemorySize, GEMM_SMEM);
    cudaFuncSetAttribute(k_gemm<1>, cudaFuncAttributeMaxDynamicSharedMemorySize, GEMM_SMEM);

    k_cvtw<<<FF * FF / 4 / 256, 256>>>(W1, w1);
    k_cvtw<<<FF * FF / 4 / 256, 256>>>(W2, w2);

    int nwarps = BB * QQ + BB * CC;
    k_dots<<<(nwarps + 7) / 8, 256>>>(qst, ctx, wq, wc);
    k_attn<<<dim3(CC / 128, BB), 256, K1_SMEM_BYTES>>>(ctx, qst, wm);
    k_q2c<<<BB, 256>>>(ctx);
    k_build_att<<<MM, 256>>>(ctx);

    k_gemm<0><<<dim3(MM / 128, FF / 128), 256, GEMM_SMEM>>>(a16, w1, b1, mask, nullptr);
    k_gemm<1><<<dim3(MM / 128, FF / 128), 256, GEMM_SMEM>>>(h16, w2, b2, mask, out);
}